// round 3
// baseline (speedup 1.0000x reference)
#include <cuda_runtime.h>
#include <cstdint>

#define TT 4096
#define DD 2048
#define HH 8192
#define NE 8
#define RRK 16
#define ER 128
#define SCAL 2.0f

#define BM 128
#define BN 256
#define BK 32
#define NS 4
#define ASZ (BM * BK * 4)            // 16 KB
#define STAGE ((BM + BN) * BK * 4)   // 48 KB
#define SMEMSZ (NS * STAGE)          // 192 KB

// ---------------- scratch (device globals) ------------------------------------
__device__ float g_W1r[(size_t)HH * DD];
__device__ float g_W2r[(size_t)DD * HH];
__device__ float g_B1r[(size_t)NE * HH * RRK];
__device__ float g_B2r[(size_t)NE * DD * RRK];
__device__ float g_Xr [(size_t)TT * DD];
__device__ float g_Y  [(size_t)TT * HH];
__device__ float g_Z1 [TT * ER];
__device__ float g_Z2 [TT * ER];

// ---------------- helpers ------------------------------------------------------
__device__ __forceinline__ float tf32r(float x) {
    uint32_t u;
    asm("cvt.rna.tf32.f32 %0, %1;" : "=r"(u) : "f"(x));
    return __uint_as_float(u);
}
__device__ __forceinline__ void cp16(uint32_t s, const void* g) {
    asm volatile("cp.async.ca.shared.global [%0], [%1], 16;" :: "r"(s), "l"(g));
}
__device__ __forceinline__ uint32_t smem_u32(const void* p) {
    uint32_t a;
    asm("{ .reg .u64 t; cvta.to.shared.u64 t, %1; cvt.u32.u64 %0, t; }" : "=r"(a) : "l"(p));
    return a;
}
__device__ __forceinline__ float gelu_new_f(float x) {
    float x3 = x * x * x;
    float inner = 0.7978845608028654f * (x + 0.044715f * x3);
    return 0.5f * x * (1.0f + tanhf(inner));
}
__device__ __forceinline__ void mma_tf32(float* c, const uint32_t* a, const uint32_t* b) {
    asm volatile(
        "mma.sync.aligned.m16n8k8.row.col.f32.tf32.tf32.f32 "
        "{%0,%1,%2,%3}, {%4,%5,%6,%7}, {%8,%9}, {%0,%1,%2,%3};"
        : "+f"(c[0]), "+f"(c[1]), "+f"(c[2]), "+f"(c[3])
        : "r"(a[0]), "r"(a[1]), "r"(a[2]), "r"(a[3]), "r"(b[0]), "r"(b[1]));
}
#define LDSM4(d, a) \
    asm volatile("ldmatrix.sync.aligned.m8n8.x4.shared.b16 {%0,%1,%2,%3}, [%4];" \
        : "=r"((d)[0]), "=r"((d)[1]), "=r"((d)[2]), "=r"((d)[3]) : "r"(a))

// ---------------- tf32 rounding copy -------------------------------------------
__global__ void round_tf32_k(float* __restrict__ dst, const float* __restrict__ src, int n4) {
    int i = blockIdx.x * blockDim.x + threadIdx.x;
    if (i < n4) {
        float4 v = reinterpret_cast<const float4*>(src)[i];
        v.x = tf32r(v.x); v.y = tf32r(v.y); v.z = tf32r(v.z); v.w = tf32r(v.w);
        reinterpret_cast<float4*>(dst)[i] = v;
    }
}

// ---------------- per-token rank-16 lora z -------------------------------------
template<int KD>
__global__ void lora_z_k(const float* __restrict__ X, const float* __restrict__ A,
                         const int* __restrict__ eidx, float* __restrict__ Z) {
    int t = blockIdx.x;
    int e = eidx[t];
    int lane = threadIdx.x & 31, w = threadIdx.x >> 5;
    if (threadIdx.x < ER) Z[t * ER + threadIdx.x] = 0.f;
    __syncthreads();
    const float* a = A + ((size_t)e * RRK + w) * KD;
    const float* x = X + (size_t)t * KD;
    float s = 0.f;
    for (int i = lane * 4; i < KD; i += 128) {
        float4 xv = *reinterpret_cast<const float4*>(x + i);
        float4 av = *reinterpret_cast<const float4*>(a + i);
        s += xv.x * av.x + xv.y * av.y + xv.z * av.z + xv.w * av.w;
    }
    #pragma unroll
    for (int o = 16; o; o >>= 1) s += __shfl_xor_sync(0xffffffffu, s, o);
    if (lane == 0) Z[t * ER + e * RRK + w] = tf32r(SCAL * s);
}

// ---------------- tf32 GEMM via mma.sync + ldmatrix ----------------------------
// C[T,N] = [A0|AL] @ [W|BL]^T (+bias, opt gelu).
// SMEM tile layout: blocks of (8 rows x 4 tf32) = 128B, indexed [row>>3][k>>2].
template<int K0, bool GELU>
__global__ void __launch_bounds__(256, 1)
moe_gemm_k(const float* __restrict__ A0, const float* __restrict__ AL,
           const float* __restrict__ W,  const float* __restrict__ BL,
           const float* __restrict__ bias, float* __restrict__ C, int Nsz) {
    constexpr int NK = (K0 + ER) / BK;

    extern __shared__ __align__(1024) char smem[];
    const uint32_t smemU = smem_u32(smem);

    const int tid  = threadIdx.x;
    const int wid  = tid >> 5, lane = tid & 31;
    const int wm   = wid >> 2, wn = wid & 3;          // 2 x 4 warp grid, 64x64 each
    const int grp  = lane >> 2, tig = lane & 3;
    const int g8   = lane >> 3, r8 = lane & 7;        // ldmatrix lane mapping
    const int lr   = tid >> 3, lc = tid & 7;          // loader: 32 rows x 8 cols
    const int m0   = blockIdx.y * BM, n0 = blockIdx.x * BN;

    // per-lane ldmatrix base offsets (within a stage)
    const uint32_t laneA = smemU + (uint32_t)(wm * 8192 + (g8 & 1) * 1024 + (g8 >> 1) * 128 + r8 * 16);
    const uint32_t laneB = smemU + (uint32_t)(ASZ + wn * 8192 + (g8 >> 1) * 1024 + (g8 & 1) * 128 + r8 * 16);

    float acc[4][8][4];
    #pragma unroll
    for (int i = 0; i < 4; i++)
        #pragma unroll
        for (int j = 0; j < 8; j++)
            #pragma unroll
            for (int c = 0; c < 4; c++) acc[i][j][c] = 0.f;

    auto load_stage = [&](int kt, int s) {
        uint32_t base = smemU + s * STAGE;
        int kk = kt * BK + lc * 4;
        #pragma unroll
        for (int p = 0; p < 4; p++) {
            int m = lr + p * 32;
            const float* gp = (kk < K0)
                ? A0 + (size_t)(m0 + m) * K0 + kk
                : AL + (size_t)(m0 + m) * ER + (kk - K0);
            cp16(base + (uint32_t)(((m >> 3) * 8 + lc) * 128 + (m & 7) * 16), gp);
        }
        #pragma unroll
        for (int p = 0; p < 8; p++) {
            int n = lr + p * 32;
            const float* gp;
            if (kk < K0) gp = W + (size_t)(n0 + n) * K0 + kk;
            else {
                int j = kk - K0;
                gp = BL + ((size_t)(j >> 4) * Nsz + (n0 + n)) * RRK + (j & 15);
            }
            cp16(base + (uint32_t)(ASZ + ((n >> 3) * 8 + lc) * 128 + (n & 7) * 16), gp);
        }
    };

    #pragma unroll
    for (int i = 0; i < NS; i++) {
        load_stage(i, i);
        asm volatile("cp.async.commit_group;" ::: "memory");
    }

    for (int kt = 0; kt < NK; ++kt) {
        int s = kt & (NS - 1);
        asm volatile("cp.async.wait_group 3;" ::: "memory");
        __syncthreads();

        uint32_t sa = laneA + s * STAGE;
        uint32_t sb = laneB + s * STAGE;
        #pragma unroll
        for (int s4 = 0; s4 < 4; s4++) {
            uint32_t af[4][4], bf[4][4];
            #pragma unroll
            for (int i = 0; i < 4; i++) LDSM4(af[i], sa + i * 2048 + s4 * 256);
            #pragma unroll
            for (int j2 = 0; j2 < 4; j2++) LDSM4(bf[j2], sb + j2 * 2048 + s4 * 256);
            #pragma unroll
            for (int i = 0; i < 4; i++)
                #pragma unroll
                for (int j2 = 0; j2 < 4; j2++) {
                    mma_tf32(acc[i][2 * j2 + 0], af[i], &bf[j2][0]);
                    mma_tf32(acc[i][2 * j2 + 1], af[i], &bf[j2][2]);
                }
        }
        __syncthreads();
        if (kt + NS < NK) load_stage(kt + NS, s);
        asm volatile("cp.async.commit_group;" ::: "memory");
    }

    // epilogue
    #pragma unroll
    for (int i = 0; i < 4; i++) {
        int row0 = m0 + wm * 64 + i * 16 + grp;
        #pragma unroll
        for (int j = 0; j < 8; j++) {
            int col = n0 + wn * 64 + j * 8 + 2 * tig;
            float bv0 = bias[col], bv1 = bias[col + 1];
            float2 v0, v1;
            if (GELU) {
                v0.x = tf32r(gelu_new_f(acc[i][j][0] + bv0));
                v0.y = tf32r(gelu_new_f(acc[i][j][1] + bv1));
                v1.x = tf32r(gelu_new_f(acc[i][j][2] + bv0));
                v1.y = tf32r(gelu_new_f(acc[i][j][3] + bv1));
            } else {
                v0.x = acc[i][j][0] + bv0; v0.y = acc[i][j][1] + bv1;
                v1.x = acc[i][j][2] + bv0; v1.y = acc[i][j][3] + bv1;
            }
            *reinterpret_cast<float2*>(&C[(size_t)row0 * Nsz + col]) = v0;
            *reinterpret_cast<float2*>(&C[(size_t)(row0 + 8) * Nsz + col]) = v1;
        }
    }
}

// ---------------- launch --------------------------------------------------------
extern "C" void kernel_launch(void* const* d_in, const int* in_sizes, int n_in,
                              void* d_out, int out_size) {
    const float* x  = (const float*)d_in[0];
    const int*   ei = (const int*)  d_in[1];
    const float* W1 = (const float*)d_in[2];
    const float* b1 = (const float*)d_in[3];
    const float* A1 = (const float*)d_in[4];
    const float* B1 = (const float*)d_in[5];
    const float* W2 = (const float*)d_in[6];
    const float* b2 = (const float*)d_in[7];
    const float* A2 = (const float*)d_in[8];
    const float* B2 = (const float*)d_in[9];
    float* out = (float*)d_out;

    float *pW1r, *pW2r, *pB1r, *pB2r, *pXr, *pY, *pZ1, *pZ2;
    cudaGetSymbolAddress((void**)&pW1r, g_W1r);
    cudaGetSymbolAddress((void**)&pW2r, g_W2r);
    cudaGetSymbolAddress((void**)&pB1r, g_B1r);
    cudaGetSymbolAddress((void**)&pB2r, g_B2r);
    cudaGetSymbolAddress((void**)&pXr,  g_Xr);
    cudaGetSymbolAddress((void**)&pY,   g_Y);
    cudaGetSymbolAddress((void**)&pZ1,  g_Z1);
    cudaGetSymbolAddress((void**)&pZ2,  g_Z2);

    cudaFuncSetAttribute(moe_gemm_k<DD, true>,
                         cudaFuncAttributeMaxDynamicSharedMemorySize, SMEMSZ);
    cudaFuncSetAttribute(moe_gemm_k<HH, false>,
                         cudaFuncAttributeMaxDynamicSharedMemorySize, SMEMSZ);

    int n4;
    n4 = HH * DD / 4;        round_tf32_k<<<(n4 + 255) / 256, 256>>>(pW1r, W1, n4);
    n4 = DD * HH / 4;        round_tf32_k<<<(n4 + 255) / 256, 256>>>(pW2r, W2, n4);
    n4 = NE * HH * RRK / 4;  round_tf32_k<<<(n4 + 255) / 256, 256>>>(pB1r, B1, n4);
    n4 = NE * DD * RRK / 4;  round_tf32_k<<<(n4 + 255) / 256, 256>>>(pB2r, B2, n4);
    n4 = TT * DD / 4;        round_tf32_k<<<(n4 + 255) / 256, 256>>>(pXr,  x,  n4);

    lora_z_k<DD><<<TT, 512>>>(x, A1, ei, pZ1);

    moe_gemm_k<DD, true><<<dim3(HH / BN, TT / BM), 256, SMEMSZ>>>(
        pXr, pZ1, pW1r, pB1r, b1, pY, HH);

    lora_z_k<HH><<<TT, 512>>>(pY, A2, ei, pZ2);

    moe_gemm_k<HH, false><<<dim3(DD / BN, TT / BM), 256, SMEMSZ>>>(
        pY, pZ2, pW2r, pB2r, b2, out, DD);
}